// round 2
// baseline (speedup 1.0000x reference)
#include <cuda_runtime.h>

#define ROWS    128          // rows per block
#define THREADS 128
#define D       64           // emb dim
#define D4      16           // emb dim in float4
#define E       6            // experts
#define STRIDE4 17           // float4 row stride in smem (68 floats: pad 4 -> conflict-free LDS.128)

__global__ __launch_bounds__(THREADS)
void gate_kernel(const float* __restrict__ h,
                 const float* __restrict__ W,
                 const float* __restrict__ b,
                 float* __restrict__ out,
                 int n)
{
    __shared__ float4 sh[ROWS * STRIDE4];   // 128 * 17 * 16B = 34816 B
    __shared__ float4 sw[E * D4];           // 1536 B
    __shared__ float  sb[E];

    const int tid = threadIdx.x;
    const long long rowBase = (long long)blockIdx.x * ROWS;

    // ---- stage W (96 float4) and b (6 floats) ----
    if (tid < E * D4)
        sw[tid] = reinterpret_cast<const float4*>(W)[tid];
    if (tid >= 96 && tid < 96 + E)
        sb[tid - 96] = b[tid - 96];

    // ---- stage h tile, fully coalesced float4 loads ----
    const float4* hg = reinterpret_cast<const float4*>(h) + rowBase * D4;
    const long long remain = (long long)n - rowBase;            // rows left
    const int maxIdx = (remain >= ROWS) ? (ROWS * D4) : (int)(remain * D4);
    #pragma unroll
    for (int i = 0; i < (ROWS * D4) / THREADS; ++i) {
        int idx = tid + i * THREADS;                             // consecutive -> coalesced
        if (idx < maxIdx) {
            int r = idx >> 4, c = idx & 15;
            sh[r * STRIDE4 + c] = hg[idx];
        }
    }
    __syncthreads();

    const long long row = rowBase + tid;
    if (row >= n) return;

    // ---- 6 dot products: h-row from smem (conflict-free), W broadcast ----
    float acc[E];
    #pragma unroll
    for (int e = 0; e < E; ++e) acc[e] = sb[e];

    const float4* hr = &sh[tid * STRIDE4];
    #pragma unroll
    for (int k = 0; k < D4; ++k) {
        float4 hv = hr[k];
        #pragma unroll
        for (int e = 0; e < E; ++e) {
            float4 wv = sw[e * D4 + k];
            acc[e] = fmaf(hv.x, wv.x,
                     fmaf(hv.y, wv.y,
                     fmaf(hv.z, wv.z,
                     fmaf(hv.w, wv.w, acc[e]))));
        }
    }

    // ---- top-2 (strict >, earliest index wins: matches jax.lax.top_k ties) ----
    int i1 = 0; float m1 = acc[0];
    #pragma unroll
    for (int e = 1; e < E; ++e)
        if (acc[e] > m1) { m1 = acc[e]; i1 = e; }

    int i2 = -1; float m2 = -3.402823466e+38f;
    #pragma unroll
    for (int e = 0; e < E; ++e)
        if (e != i1 && acc[e] > m2) { m2 = acc[e]; i2 = e; }

    // masked-renormalized softmax == 2-way softmax over {m1, m2}
    float ex = __expf(m2 - m1);          // <= 1, no overflow
    float p1 = 1.0f / (1.0f + ex);
    float p2 = ex * p1;

    float o[E];
    #pragma unroll
    for (int e = 0; e < E; ++e)
        o[e] = (e == i1) ? p1 : ((e == i2) ? p2 : 0.0f);

    // ---- 3x STG.64 (rows are 24B -> 8B aligned) ----
    float2* op = reinterpret_cast<float2*>(out + row * (long long)E);
    op[0] = make_float2(o[0], o[1]);
    op[1] = make_float2(o[2], o[3]);
    op[2] = make_float2(o[4], o[5]);
}

extern "C" void kernel_launch(void* const* d_in, const int* in_sizes, int n_in,
                              void* d_out, int out_size)
{
    const float* h = (const float*)d_in[0];
    const float* W = (const float*)d_in[1];
    const float* b = (const float*)d_in[2];
    float* out = (float*)d_out;

    int n = in_sizes[0] / D;                     // number of rows
    int grid = (n + ROWS - 1) / ROWS;
    gate_kernel<<<grid, THREADS>>>(h, W, b, out, n);
}

// round 6
// speedup vs baseline: 1.0879x; 1.0879x over previous
#include <cuda_runtime.h>
#include <cstdint>

#define D        64
#define D4       16
#define E        6
#define ROWS     128               // rows per tile
#define THREADS  128
#define ROW_PAD  272               // 256 B row + 16 B pad (17 float4 -> conflict-free LDS.128)
#define SLOT_BYTES (ROWS * ROW_PAD)        // 34816
#define OFF_SLOT0  0
#define OFF_SLOT1  SLOT_BYTES              // 34816
#define OFF_SW     (2 * SLOT_BYTES)        // 69632
#define OFF_SB     (OFF_SW + E * D * 4)    // 71168
#define OFF_MB0    (OFF_SB + 32)           // 71200 (8-aligned)
#define OFF_MB1    (OFF_MB0 + 8)           // 71208
#define SMEM_TOTAL (OFF_MB1 + 8 + 48)      // 71264 (padded)

// ---------------- PTX helpers ----------------
__device__ __forceinline__ uint32_t smem_u32(const void* p) {
    uint32_t a;
    asm("{ .reg .u64 t; cvta.to.shared.u64 t, %1; cvt.u32.u64 %0, t; }" : "=r"(a) : "l"(p));
    return a;
}
#define MBAR_INIT(addr, cnt) \
    asm volatile("mbarrier.init.shared.b64 [%0], %1;" :: "r"(addr), "r"(cnt) : "memory")
#define MBAR_EXPECT_TX(addr, bytes) \
    asm volatile("mbarrier.arrive.expect_tx.shared.b64 _, [%0], %1;" :: "r"(addr), "r"(bytes) : "memory")
#define MBAR_ARRIVE(addr) \
    asm volatile("mbarrier.arrive.shared.b64 _, [%0];" :: "r"(addr) : "memory")
#define MBAR_WAIT(addr, parity) do {                                              \
    uint32_t _m = (addr), _p = (parity);                                          \
    asm volatile(                                                                 \
        "{\n\t.reg .pred P1;\n\t"                                                 \
        "WL_%=:\n\t"                                                              \
        "mbarrier.try_wait.parity.acquire.cta.shared::cta.b64 P1, [%0], %1, 0x989680;\n\t" \
        "@P1 bra.uni WD_%=;\n\t"                                                  \
        "bra.uni WL_%=;\n\t"                                                      \
        "WD_%=:\n\t}"                                                             \
        :: "r"(_m), "r"(_p) : "memory");                                          \
} while (0)
#define BULK_CP(dst_smem, src_gmem, bytes, mbar) \
    asm volatile("cp.async.bulk.shared::cta.global.mbarrier::complete_tx::bytes [%0], [%1], %2, [%3];" \
                 :: "r"(dst_smem), "l"(src_gmem), "r"(bytes), "r"(mbar) : "memory")
#define FMA_F32X2(d, a, b, c) \
    asm("fma.rn.f32x2 %0, %1, %2, %3;" : "=l"(d) : "l"(a), "l"(b), "l"(c))
#define UNPACK2(lo, hi, v) \
    asm("mov.b64 {%0, %1}, %2;" : "=f"(lo), "=f"(hi) : "l"(v))

// ---------------- kernel ----------------
__global__ __launch_bounds__(THREADS)
void gate_kernel(const float* __restrict__ h,
                 const float* __restrict__ W,
                 const float* __restrict__ b,
                 float* __restrict__ out,
                 int n, int ntiles)
{
    extern __shared__ char smem[];
    const uint32_t sbase = smem_u32(smem);
    const uint32_t mb[2] = { sbase + OFF_MB0, sbase + OFF_MB1 };
    const int tid = threadIdx.x;

    // W (as ulonglong2 rows of 4 floats) and bias staged once per block
    float4* sw4 = reinterpret_cast<float4*>(smem + OFF_SW);
    float*  sb  = reinterpret_cast<float*>(smem + OFF_SB);
    if (tid < E * D4) sw4[tid] = reinterpret_cast<const float4*>(W)[tid];
    if (tid >= 96 && tid < 96 + E) sb[tid - 96] = b[tid - 96];
    if (tid == 0) { MBAR_INIT(mb[0], THREADS); MBAR_INIT(mb[1], THREADS); }
    __syncthreads();

    const int stride = gridDim.x;
    const int t0 = blockIdx.x;

    // prefetch: each thread copies its own row (expect_tx paired per-thread)
    auto prefetch = [&](int tile, int slot) {
        long long row = (long long)tile * ROWS + tid;
        uint32_t dst = sbase + slot * SLOT_BYTES + tid * ROW_PAD;
        if (row < n) {
            MBAR_EXPECT_TX(mb[slot], 256);
            BULK_CP(dst, h + row * D, 256, mb[slot]);
        } else {
            MBAR_ARRIVE(mb[slot]);
        }
    };

    prefetch(t0, 0);
    if (t0 + stride < ntiles) prefetch(t0 + stride, 1);

    const ulonglong2* swq = reinterpret_cast<const ulonglong2*>(smem + OFF_SW);

    int ph0 = 0, ph1 = 0;
    for (int t = t0; t < ntiles; ) {
        #pragma unroll
        for (int s = 0; s < 2; ++s) {
            if (t >= ntiles) break;
            if (s == 0) { MBAR_WAIT(mb[0], ph0); ph0 ^= 1; }
            else        { MBAR_WAIT(mb[1], ph1); ph1 ^= 1; }

            long long row = (long long)t * ROWS + tid;
            if (row < n) {
                const ulonglong2* hr =
                    reinterpret_cast<const ulonglong2*>(smem + s * SLOT_BYTES + tid * ROW_PAD);

                uint64_t acc0[E], acc1[E];
                #pragma unroll
                for (int e = 0; e < E; ++e) { acc0[e] = 0ull; acc1[e] = 0ull; }

                #pragma unroll
                for (int k = 0; k < D4; ++k) {
                    ulonglong2 hv = hr[k];
                    #pragma unroll
                    for (int e = 0; e < E; ++e) {
                        ulonglong2 wv = swq[e * D4 + k];     // uniform -> LDS broadcast
                        FMA_F32X2(acc0[e], hv.x, wv.x, acc0[e]);
                        FMA_F32X2(acc1[e], hv.y, wv.y, acc1[e]);
                    }
                }

                float g[E];
                #pragma unroll
                for (int e = 0; e < E; ++e) {
                    float a0, a1, a2, a3;
                    UNPACK2(a0, a1, acc0[e]);
                    UNPACK2(a2, a3, acc1[e]);
                    g[e] = ((a0 + a2) + (a1 + a3)) + sb[e];
                }

                // top-2, strict >, earliest index wins (matches jax.lax.top_k)
                int i1 = 0; float m1 = g[0];
                #pragma unroll
                for (int e = 1; e < E; ++e) if (g[e] > m1) { m1 = g[e]; i1 = e; }
                int i2 = -1; float m2 = -3.402823466e+38f;
                #pragma unroll
                for (int e = 0; e < E; ++e) if (e != i1 && g[e] > m2) { m2 = g[e]; i2 = e; }

                float ex = __expf(m2 - m1);
                float p1 = 1.0f / (1.0f + ex);
                float p2 = ex * p1;

                float o[E];
                #pragma unroll
                for (int e = 0; e < E; ++e)
                    o[e] = (e == i1) ? p1 : ((e == i2) ? p2 : 0.0f);

                float2* op = reinterpret_cast<float2*>(out + row * (long long)E);
                op[0] = make_float2(o[0], o[1]);
                op[1] = make_float2(o[2], o[3]);
                op[2] = make_float2(o[4], o[5]);
            }

            __syncthreads();                       // slot s fully consumed
            int tn = t + 2 * stride;               // refill slot s
            if (tn < ntiles) prefetch(tn, s);
            t += stride;
        }
    }
}

extern "C" void kernel_launch(void* const* d_in, const int* in_sizes, int n_in,
                              void* d_out, int out_size)
{
    const float* h = (const float*)d_in[0];
    const float* W = (const float*)d_in[1];
    const float* b = (const float*)d_in[2];
    float* out = (float*)d_out;

    int n = in_sizes[0] / D;
    int ntiles = (n + ROWS - 1) / ROWS;

    cudaFuncSetAttribute(gate_kernel, cudaFuncAttributeMaxDynamicSharedMemorySize, SMEM_TOTAL);

    int grid = 148 * 3;                 // 3 blocks/SM resident (71 KB smem each)
    if (grid > ntiles) grid = ntiles;
    gate_kernel<<<grid, THREADS, SMEM_TOTAL>>>(h, W, b, out, n, ntiles);
}

// round 7
// speedup vs baseline: 1.1517x; 1.0587x over previous
#include <cuda_runtime.h>
#include <cstdint>

#define D        64
#define D4       16
#define E        6
#define ROWS     128               // rows per tile
#define THREADS  256               // 2 threads per row
#define ROW_PAD  272               // 256 B row + 16 B pad -> conflict-free LDS.128
#define SLOT_BYTES (ROWS * ROW_PAD)        // 34816
#define OFF_SW     (2 * SLOT_BYTES)        // 69632
#define OFF_SB     (OFF_SW + E * D * 4)    // 71168
#define OFF_MB0    (OFF_SB + 32)           // 71200
#define OFF_MB1    (OFF_MB0 + 8)           // 71208
#define SMEM_TOTAL (OFF_MB1 + 8 + 48)      // 71264

// ---------------- PTX helpers ----------------
__device__ __forceinline__ uint32_t smem_u32(const void* p) {
    uint32_t a;
    asm("{ .reg .u64 t; cvta.to.shared.u64 t, %1; cvt.u32.u64 %0, t; }" : "=r"(a) : "l"(p));
    return a;
}
#define MBAR_INIT(addr, cnt) \
    asm volatile("mbarrier.init.shared.b64 [%0], %1;" :: "r"(addr), "r"(cnt) : "memory")
#define MBAR_EXPECT_TX(addr, bytes) \
    asm volatile("mbarrier.arrive.expect_tx.shared.b64 _, [%0], %1;" :: "r"(addr), "r"(bytes) : "memory")
#define MBAR_ARRIVE(addr) \
    asm volatile("mbarrier.arrive.shared.b64 _, [%0];" :: "r"(addr) : "memory")
#define MBAR_WAIT(addr, parity) do {                                              \
    uint32_t _m = (addr), _p = (parity);                                          \
    asm volatile(                                                                 \
        "{\n\t.reg .pred P1;\n\t"                                                 \
        "WL_%=:\n\t"                                                              \
        "mbarrier.try_wait.parity.acquire.cta.shared::cta.b64 P1, [%0], %1, 0x989680;\n\t" \
        "@P1 bra.uni WD_%=;\n\t"                                                  \
        "bra.uni WL_%=;\n\t"                                                      \
        "WD_%=:\n\t}"                                                             \
        :: "r"(_m), "r"(_p) : "memory");                                          \
} while (0)
#define BULK_CP(dst_smem, src_gmem, bytes, mbar) \
    asm volatile("cp.async.bulk.shared::cta.global.mbarrier::complete_tx::bytes [%0], [%1], %2, [%3];" \
                 :: "r"(dst_smem), "l"(src_gmem), "r"(bytes), "r"(mbar) : "memory")
#define FMA_F32X2(d, a, b, c) \
    asm("fma.rn.f32x2 %0, %1, %2, %3;" : "=l"(d) : "l"(a), "l"(b), "l"(c))
#define UNPACK2(lo, hi, v) \
    asm("mov.b64 {%0, %1}, %2;" : "=f"(lo), "=f"(hi) : "l"(v))

// ---------------- kernel ----------------
__global__ __launch_bounds__(THREADS, 3)
void gate_kernel(const float* __restrict__ h,
                 const float* __restrict__ W,
                 const float* __restrict__ b,
                 float* __restrict__ out,
                 int n, int ntiles)
{
    extern __shared__ char smem[];
    const uint32_t sbase = smem_u32(smem);
    const uint32_t mb[2] = { sbase + OFF_MB0, sbase + OFF_MB1 };
    const int tid  = threadIdx.x;
    const int lane = tid & 31;
    // 2 threads per row: lanes l and l^16 share row (w*16 + (l&15)); half = l>>4 bit
    const int rowInTile = (tid >> 5) * 16 + (lane & 15);
    const int half      = (lane >> 4) & 1;

    float4* sw4 = reinterpret_cast<float4*>(smem + OFF_SW);
    float*  sb  = reinterpret_cast<float*>(smem + OFF_SB);
    if (tid < E * D4) sw4[tid] = reinterpret_cast<const float4*>(W)[tid];
    if (tid >= 96 && tid < 96 + E) sb[tid - 96] = b[tid - 96];
    if (tid == 0) { MBAR_INIT(mb[0], 128); MBAR_INIT(mb[1], 128); }
    __syncthreads();

    const int stride = gridDim.x;
    const int t0 = blockIdx.x;

    // prefetch: threads 0..127 each copy one row (expect_tx paired per-thread)
    auto prefetch = [&](int tile, int slot) {
        if (tid < 128) {
            long long row = (long long)tile * ROWS + tid;
            uint32_t dst = sbase + slot * SLOT_BYTES + tid * ROW_PAD;
            if (row < n) {
                MBAR_EXPECT_TX(mb[slot], 256);
                BULK_CP(dst, h + row * D, 256, mb[slot]);
            } else {
                MBAR_ARRIVE(mb[slot]);
            }
        }
    };

    prefetch(t0, 0);
    if (t0 + stride < ntiles) prefetch(t0 + stride, 1);

    int ph0 = 0, ph1 = 0;
    for (int t = t0; t < ntiles; ) {
        #pragma unroll
        for (int s = 0; s < 2; ++s) {
            if (t >= ntiles) break;
            if (s == 0) { MBAR_WAIT(mb[0], ph0); ph0 ^= 1; }
            else        { MBAR_WAIT(mb[1], ph1); ph1 ^= 1; }

            long long row = (long long)t * ROWS + rowInTile;
            if (row < n) {
                // this thread's half-row: 8 float4 (32 floats)
                const ulonglong2* hr = reinterpret_cast<const ulonglong2*>(
                    smem + s * SLOT_BYTES + rowInTile * ROW_PAD + half * 128);
                // W half-rows: phase-uniform addresses -> LDS broadcast
                const ulonglong2* swq = reinterpret_cast<const ulonglong2*>(
                    smem + OFF_SW + half * 128);

                uint64_t acc0[E], acc1[E];
                #pragma unroll
                for (int e = 0; e < E; ++e) { acc0[e] = 0ull; acc1[e] = 0ull; }

                #pragma unroll
                for (int k = 0; k < 8; ++k) {
                    ulonglong2 hv = hr[k];
                    #pragma unroll
                    for (int e = 0; e < E; ++e) {
                        ulonglong2 wv = swq[e * D4 + k];   // (e*64 + half*32 + k*4) floats
                        FMA_F32X2(acc0[e], hv.x, wv.x, acc0[e]);
                        FMA_F32X2(acc1[e], hv.y, wv.y, acc1[e]);
                    }
                }

                float g[E];
                #pragma unroll
                for (int e = 0; e < E; ++e) {
                    float a0, a1, a2, a3;
                    UNPACK2(a0, a1, acc0[e]);
                    UNPACK2(a2, a3, acc1[e]);
                    float mine  = ((a0 + a2) + (a1 + a3));
                    float other = __shfl_xor_sync(0xffffffffu, mine, 16);
                    float lo = half ? other : mine;
                    float hi = half ? mine  : other;
                    g[e] = (lo + hi) + sb[e];
                }

                // top-2, strict >, earliest index wins (matches jax.lax.top_k)
                int i1 = 0; float m1 = g[0];
                #pragma unroll
                for (int e = 1; e < E; ++e) if (g[e] > m1) { m1 = g[e]; i1 = e; }
                int i2 = -1; float m2 = -3.402823466e+38f;
                #pragma unroll
                for (int e = 0; e < E; ++e) if (e != i1 && g[e] > m2) { m2 = g[e]; i2 = e; }

                float ex = __expf(m2 - m1);
                float p1 = 1.0f / (1.0f + ex);
                float p2 = ex * p1;

                float o[E];
                #pragma unroll
                for (int e = 0; e < E; ++e)
                    o[e] = (e == i1) ? p1 : ((e == i2) ? p2 : 0.0f);

                // split the 24B row store across the lane pair (all STG.64, 8B aligned)
                float2* op = reinterpret_cast<float2*>(out + row * (long long)E);
                if (half == 0) {
                    op[0] = make_float2(o[0], o[1]);
                    op[1] = make_float2(o[2], o[3]);
                } else {
                    op[2] = make_float2(o[4], o[5]);
                }
            }

            __syncthreads();                       // slot s fully consumed
            int tn = t + 2 * stride;               // refill slot s
            if (tn < ntiles) prefetch(tn, s);
            t += stride;
        }
    }
}

extern "C" void kernel_launch(void* const* d_in, const int* in_sizes, int n_in,
                              void* d_out, int out_size)
{
    const float* h = (const float*)d_in[0];
    const float* W = (const float*)d_in[1];
    const float* b = (const float*)d_in[2];
    float* out = (float*)d_out;

    int n = in_sizes[0] / D;
    int ntiles = (n + ROWS - 1) / ROWS;

    cudaFuncSetAttribute(gate_kernel, cudaFuncAttributeMaxDynamicSharedMemorySize, SMEM_TOTAL);

    int grid = 148 * 3;                 // 3 blocks/SM resident (71 KB smem each)
    if (grid > ntiles) grid = ntiles;
    gate_kernel<<<grid, THREADS, SMEM_TOTAL>>>(h, W, b, out, n, ntiles);
}